// round 6
// baseline (speedup 1.0000x reference)
#include <cuda_runtime.h>
#include <cstdint>
#include <math.h>

// Problem constants
#define Bn 4
#define Sn 2048
#define Dn 2048
#define Hn 16
#define DHn 128
#define TDn 6144            // 3*D
#define NROWS (Bn*Sn)       // 8192

// Scratch (device globals; no cudaMalloc allowed)
__device__ float g_qkv[(size_t)NROWS * TDn];   // 201 MB
__device__ float g_y[(size_t)NROWS * Dn];      // 67 MB  (tf32-formatted)
__device__ float g_xt[(size_t)NROWS * Dn];     // 67 MB  x  pre-converted
__device__ float g_wq[(size_t)TDn * Dn];       // 50 MB  qkv_w pre-converted
__device__ float g_wo[(size_t)Dn * Dn];        // 17 MB  out_w pre-converted

__device__ __forceinline__ uint32_t f2tf32(float x) {
    uint32_t r;
    asm("cvt.rna.tf32.f32 %0, %1;" : "=r"(r) : "f"(x));
    return r;
}

__device__ __forceinline__ void mma_tf32(float* d,
                                         uint32_t a0, uint32_t a1,
                                         uint32_t a2, uint32_t a3,
                                         uint32_t b0, uint32_t b1) {
    asm volatile(
        "mma.sync.aligned.m16n8k8.row.col.f32.tf32.tf32.f32 "
        "{%0,%1,%2,%3}, {%4,%5,%6,%7}, {%8,%9}, {%0,%1,%2,%3};"
        : "+f"(d[0]), "+f"(d[1]), "+f"(d[2]), "+f"(d[3])
        : "r"(a0), "r"(a1), "r"(a2), "r"(a3), "r"(b0), "r"(b1));
}

__device__ __forceinline__ void cp16(void* smem_ptr, const void* gptr) {
    uint32_t sa = (uint32_t)__cvta_generic_to_shared(smem_ptr);
    asm volatile("cp.async.cg.shared.global [%0], [%1], 16;"
                 :: "r"(sa), "l"(gptr));
}
#define CP_COMMIT() asm volatile("cp.async.commit_group;" ::: "memory")
#define CP_WAIT(n)  asm volatile("cp.async.wait_group %0;" :: "n"(n) : "memory")

// ---------------------------------------------------------------------------
// Pre-convert fp32 -> tf32-formatted fp32 (vectorized)
// ---------------------------------------------------------------------------
__global__ __launch_bounds__(256) void conv_tf32_kernel(
    const float* __restrict__ in, float* __restrict__ out, int n4)
{
    int i = blockIdx.x * blockDim.x + threadIdx.x;
    if (i >= n4) return;
    float4 v = ((const float4*)in)[i];
    uint4 u = make_uint4(f2tf32(v.x), f2tf32(v.y), f2tf32(v.z), f2tf32(v.w));
    ((uint4*)out)[i] = u;
}

// ---------------------------------------------------------------------------
// cp.async tf32 GEMM: C[M,N] = A[M,K] @ W[N,K]^T + bias[N]
// A, W must already be tf32-formatted fp32.
// CTA 128x256, 8 warps (2m x 4n), warp tile 64x64. KC=16, 4 stages.
// smem stride 20 floats (conflict-free fragment LDS).
// ---------------------------------------------------------------------------
#define KC2 16
#define STG 4
#define STR2 20
#define ATILE (128 * STR2)                    // 2560 floats (10KB)
#define BTILE (256 * STR2)                    // 5120 floats (20KB)
#define STAGE_F (ATILE + BTILE)
#define GEMM2_SMEM (STG * STAGE_F * 4)        // 122880 bytes

__global__ void __launch_bounds__(256) mma_gemm_ca(
    const float* __restrict__ A, const float* __restrict__ W,
    const float* __restrict__ bias, float* __restrict__ C,
    int M, int N, int K)
{
    extern __shared__ float sm[];
    const int tid = threadIdx.x;
    const int wid = tid >> 5;
    const int lid = tid & 31;
    const int g   = lid >> 2;
    const int tg  = lid & 3;
    const int wm  = wid >> 2;       // 0..1
    const int wn  = wid & 3;        // 0..3
    const int m0 = blockIdx.y << 7;
    const int n0 = blockIdx.x << 8;

    const float* Abase = A + (size_t)m0 * K;
    const float* Wbase = W + (size_t)n0 * K;

    // load mapping: A: 512 16B-slots, B: 1024 slots, 256 threads
    const int arow = tid >> 1;             // A: 2 iters, rows 0..127
    const int ac4  = (tid & 1) << 3;       // col 0 or 8 (two float4 each)
    const int brow = tid >> 2;             // B: 4 iters of 64 rows
    const int bc4  = (tid & 3) << 2;       // col 0,4,8,12

    float acc[4][8][4];
#pragma unroll
    for (int mi = 0; mi < 4; mi++)
#pragma unroll
        for (int ni = 0; ni < 8; ni++)
#pragma unroll
            for (int r = 0; r < 4; r++) acc[mi][ni][r] = 0.f;

    const int nc = K / KC2;

    auto issue_load = [&](int stage, int chunk) {
        const int k0 = chunk * KC2;
        float* As = sm + stage * STAGE_F;
        float* Bs = As + ATILE;
        // A: each thread 2 cp16 (row, cols ac4 and ac4+4)
        cp16(&As[arow * STR2 + ac4],     Abase + (size_t)arow * K + k0 + ac4);
        cp16(&As[arow * STR2 + ac4 + 4], Abase + (size_t)arow * K + k0 + ac4 + 4);
        // B: 4 cp16
#pragma unroll
        for (int i = 0; i < 4; i++) {
            const int row = brow + i * 64;
            cp16(&Bs[row * STR2 + bc4], Wbase + (size_t)row * K + k0 + bc4);
        }
    };

    auto compute = [&](int stage) {
        const float* As = sm + stage * STAGE_F;
        const float* Bs = As + ATILE;
#pragma unroll
        for (int ks = 0; ks < 2; ks++) {
            const int kc = ks * 8;
            uint32_t bf[8][2];
#pragma unroll
            for (int ni = 0; ni < 8; ni++) {
                const float* bp = &Bs[(wn * 64 + ni * 8 + g) * STR2 + kc + tg];
                bf[ni][0] = __float_as_uint(bp[0]);
                bf[ni][1] = __float_as_uint(bp[4]);
            }
#pragma unroll
            for (int mi = 0; mi < 4; mi++) {
                const float* ap = &As[(wm * 64 + mi * 16 + g) * STR2 + kc + tg];
                uint32_t a0 = __float_as_uint(ap[0]);
                uint32_t a1 = __float_as_uint(ap[8 * STR2]);
                uint32_t a2 = __float_as_uint(ap[4]);
                uint32_t a3 = __float_as_uint(ap[8 * STR2 + 4]);
#pragma unroll
                for (int ni = 0; ni < 8; ni++)
                    mma_tf32(acc[mi][ni], a0, a1, a2, a3,
                             bf[ni][0], bf[ni][1]);
            }
        }
    };

    // prologue: fill STG-1 stages
#pragma unroll
    for (int s = 0; s < STG - 1; s++) {
        issue_load(s, s);
        CP_COMMIT();
    }

    for (int c = 0; c < nc; c++) {
        CP_WAIT(STG - 2);
        __syncthreads();
        const int nxt = c + STG - 1;
        if (nxt < nc) issue_load(nxt & (STG - 1), nxt);
        CP_COMMIT();
        compute(c & (STG - 1));
    }

    // epilogue: write C + bias
#pragma unroll
    for (int ni = 0; ni < 8; ni++) {
        const int col = n0 + wn * 64 + ni * 8 + 2 * tg;
        const float2 bj = *(const float2*)&bias[col];
#pragma unroll
        for (int mi = 0; mi < 4; mi++) {
            const int row = m0 + wm * 64 + mi * 16 + g;
            float2 o0, o1;
            o0.x = acc[mi][ni][0] + bj.x;
            o0.y = acc[mi][ni][1] + bj.y;
            o1.x = acc[mi][ni][2] + bj.x;
            o1.y = acc[mi][ni][3] + bj.y;
            *(float2*)&C[(size_t)row * N + col] = o0;
            *(float2*)&C[(size_t)(row + 8) * N + col] = o1;
        }
    }
}

// ---------------------------------------------------------------------------
// RoPE applied in-place to q and k halves of g_qkv (unchanged)
// ---------------------------------------------------------------------------
__global__ __launch_bounds__(256) void rope_kernel(float* __restrict__ qkv)
{
    int idx = blockIdx.x * blockDim.x + threadIdx.x;
    const int total = Bn * Sn * Hn * (DHn / 2);
    if (idx >= total) return;

    int d2 = idx & 63;
    int h  = (idx >> 6) & 15;
    int bs = idx >> 10;
    int s  = bs & (Sn - 1);

    float freq  = powf(10000.0f, -(float)d2 / 64.0f);
    float angle = (float)s * freq;
    float sn, cs;
    sincosf(angle, &sn, &cs);

    size_t base = (size_t)bs * TDn + h * DHn + 2 * d2;

    float x1 = qkv[base], x2 = qkv[base + 1];
    qkv[base]     = x1 * cs - x2 * sn;
    qkv[base + 1] = x1 * sn + x2 * cs;
    float y1 = qkv[base + Dn], y2 = qkv[base + Dn + 1];
    qkv[base + Dn]     = y1 * cs - y2 * sn;
    qkv[base + Dn + 1] = y1 * sn + y2 * cs;
}

// ---------------------------------------------------------------------------
// Tensor-core flash attention (causal), tf32 mma. (unchanged R5)
// ---------------------------------------------------------------------------
#define KSTR 132
#define VSTR 136
#define PSTRW 132
#define FA_SMEM ((64 * KSTR + 64 * VSTR + 128 * PSTRW) * 4)

__global__ __launch_bounds__(256) void flash_attn_tc(
    const float* __restrict__ qkv, float* __restrict__ Y)
{
    extern __shared__ float sm[];
    float* Ks = sm;
    float* Vs = Ks + 64 * KSTR;
    float* Pw = Vs + 64 * VSTR;

    const int tid = threadIdx.x;
    const int wid = tid >> 5;
    const int lid = tid & 31;
    const int g   = lid >> 2;
    const int tg  = lid & 3;
    const int qb  = blockIdx.x;
    const int q0  = qb * 128;
    const int bh  = blockIdx.y;
    const int b   = bh >> 4;
    const int h   = bh & 15;

    const int row0 = q0 + wid * 16 + g;
    const float scale = 0.08838834764831845f;

    const float* qptr = qkv + ((size_t)(b * Sn + row0)) * TDn + h * DHn;
    uint32_t qf[16][4];
#pragma unroll
    for (int kt = 0; kt < 16; kt++) {
        qf[kt][0] = f2tf32(qptr[kt * 8 + tg] * scale);
        qf[kt][1] = f2tf32(qptr[(size_t)8 * TDn + kt * 8 + tg] * scale);
        qf[kt][2] = f2tf32(qptr[kt * 8 + tg + 4] * scale);
        qf[kt][3] = f2tf32(qptr[(size_t)8 * TDn + kt * 8 + tg + 4] * scale);
    }

    float ofr[16][4];
#pragma unroll
    for (int nt = 0; nt < 16; nt++)
#pragma unroll
        for (int r = 0; r < 4; r++) ofr[nt][r] = 0.f;

    float m0 = -1e30f, m1 = -1e30f, l0 = 0.f, l1 = 0.f;

    const float* kbase = qkv + ((size_t)(b * Sn)) * TDn + Dn + h * DHn;
    const float* vbase = kbase + Dn;
    float* prow = Pw + (wid * 16) * PSTRW;

    const int nkb = 2 * qb + 2;
    for (int kb = 0; kb < nkb; kb++) {
        __syncthreads();
        const int k0 = kb * 64;

#pragma unroll
        for (int i = 0; i < 8; i++) {
            int idx = tid + i * 256;
            int r  = idx >> 5;
            int c4 = (idx & 31) << 2;
            const size_t go = (size_t)(k0 + r) * TDn + c4;
            float4 kv = *(const float4*)(kbase + go);
            uint4 ku = make_uint4(f2tf32(kv.x), f2tf32(kv.y),
                                  f2tf32(kv.z), f2tf32(kv.w));
            *(uint4*)&Ks[r * KSTR + c4] = ku;
            float4 vv = *(const float4*)(vbase + go);
            uint4 vu = make_uint4(f2tf32(vv.x), f2tf32(vv.y),
                                  f2tf32(vv.z), f2tf32(vv.w));
            *(uint4*)&Vs[r * VSTR + c4] = vu;
        }
        __syncthreads();

        float sc[8][4];
#pragma unroll
        for (int nt = 0; nt < 8; nt++)
#pragma unroll
            for (int r = 0; r < 4; r++) sc[nt][r] = 0.f;

#pragma unroll
        for (int kt = 0; kt < 16; kt++) {
#pragma unroll
            for (int nt = 0; nt < 8; nt++) {
                const float* bp = &Ks[(nt * 8 + g) * KSTR + kt * 8 + tg];
                uint32_t b0 = __float_as_uint(bp[0]);
                uint32_t b1 = __float_as_uint(bp[4]);
                mma_tf32(sc[nt], qf[kt][0], qf[kt][1], qf[kt][2], qf[kt][3],
                         b0, b1);
            }
        }

        if (kb >= 2 * qb) {
#pragma unroll
            for (int nt = 0; nt < 8; nt++) {
                int col = k0 + nt * 8 + 2 * tg;
                if (col > row0)     sc[nt][0] = -1e30f;
                if (col + 1 > row0) sc[nt][1] = -1e30f;
                if (col > row0 + 8)     sc[nt][2] = -1e30f;
                if (col + 1 > row0 + 8) sc[nt][3] = -1e30f;
            }
        }

        float mx0 = -1e30f, mx1 = -1e30f;
#pragma unroll
        for (int nt = 0; nt < 8; nt++) {
            mx0 = fmaxf(mx0, fmaxf(sc[nt][0], sc[nt][1]));
            mx1 = fmaxf(mx1, fmaxf(sc[nt][2], sc[nt][3]));
        }
        mx0 = fmaxf(mx0, __shfl_xor_sync(0xffffffffu, mx0, 1));
        mx0 = fmaxf(mx0, __shfl_xor_sync(0xffffffffu, mx0, 2));
        mx1 = fmaxf(mx1, __shfl_xor_sync(0xffffffffu, mx1, 1));
        mx1 = fmaxf(mx1, __shfl_xor_sync(0xffffffffu, mx1, 2));

        const float mn0 = fmaxf(m0, mx0);
        const float mn1 = fmaxf(m1, mx1);
        const float a0 = __expf(m0 - mn0);
        const float a1 = __expf(m1 - mn1);
        m0 = mn0; m1 = mn1;

        float s0 = 0.f, s1 = 0.f;
#pragma unroll
        for (int nt = 0; nt < 8; nt++) {
            sc[nt][0] = __expf(sc[nt][0] - mn0);
            sc[nt][1] = __expf(sc[nt][1] - mn0);
            sc[nt][2] = __expf(sc[nt][2] - mn1);
            sc[nt][3] = __expf(sc[nt][3] - mn1);
            s0 += sc[nt][0] + sc[nt][1];
            s1 += sc[nt][2] + sc[nt][3];
        }
        s0 += __shfl_xor_sync(0xffffffffu, s0, 1);
        s0 += __shfl_xor_sync(0xffffffffu, s0, 2);
        s1 += __shfl_xor_sync(0xffffffffu, s1, 1);
        s1 += __shfl_xor_sync(0xffffffffu, s1, 2);
        l0 = l0 * a0 + s0;
        l1 = l1 * a1 + s1;

#pragma unroll
        for (int nt = 0; nt < 16; nt++) {
            ofr[nt][0] *= a0; ofr[nt][1] *= a0;
            ofr[nt][2] *= a1; ofr[nt][3] *= a1;
        }

        __syncwarp();
#pragma unroll
        for (int nt = 0; nt < 8; nt++) {
            const int col = nt * 8 + 2 * tg;
            prow[g * PSTRW + col]           = __uint_as_float(f2tf32(sc[nt][0]));
            prow[g * PSTRW + col + 1]       = __uint_as_float(f2tf32(sc[nt][1]));
            prow[(g + 8) * PSTRW + col]     = __uint_as_float(f2tf32(sc[nt][2]));
            prow[(g + 8) * PSTRW + col + 1] = __uint_as_float(f2tf32(sc[nt][3]));
        }
        __syncwarp();

#pragma unroll
        for (int kt = 0; kt < 8; kt++) {
            uint32_t pa0 = __float_as_uint(prow[g * PSTRW + kt * 8 + tg]);
            uint32_t pa1 = __float_as_uint(prow[(g + 8) * PSTRW + kt * 8 + tg]);
            uint32_t pa2 = __float_as_uint(prow[g * PSTRW + kt * 8 + tg + 4]);
            uint32_t pa3 = __float_as_uint(prow[(g + 8) * PSTRW + kt * 8 + tg + 4]);
#pragma unroll
            for (int nt = 0; nt < 16; nt++) {
                uint32_t b0 = __float_as_uint(Vs[(kt * 8 + tg) * VSTR + nt * 8 + g]);
                uint32_t b1 = __float_as_uint(Vs[(kt * 8 + tg + 4) * VSTR + nt * 8 + g]);
                mma_tf32(ofr[nt], pa0, pa1, pa2, pa3, b0, b1);
            }
        }
    }

    const float inv0 = 1.0f / l0;
    const float inv1 = 1.0f / l1;
    float* yrow = Y + ((size_t)(b * Sn + row0)) * Dn + h * DHn;
#pragma unroll
    for (int nt = 0; nt < 16; nt++) {
        const int col = nt * 8 + 2 * tg;
        float2 o0, o1;
        o0.x = __uint_as_float(f2tf32(ofr[nt][0] * inv0));
        o0.y = __uint_as_float(f2tf32(ofr[nt][1] * inv0));
        o1.x = __uint_as_float(f2tf32(ofr[nt][2] * inv1));
        o1.y = __uint_as_float(f2tf32(ofr[nt][3] * inv1));
        *(float2*)&yrow[col] = o0;
        *(float2*)&yrow[(size_t)8 * Dn + col] = o1;
    }
}

// ---------------------------------------------------------------------------
extern "C" void kernel_launch(void* const* d_in, const int* in_sizes, int n_in,
                              void* d_out, int out_size)
{
    (void)in_sizes; (void)n_in; (void)out_size;
    const float* x      = (const float*)d_in[0];
    const float* qkv_w  = (const float*)d_in[1];
    const float* qkv_b  = (const float*)d_in[2];
    const float* out_w  = (const float*)d_in[3];
    const float* out_b  = (const float*)d_in[4];
    float* out = (float*)d_out;

    float *qkv, *y, *xt, *wq, *wo;
    cudaGetSymbolAddress((void**)&qkv, g_qkv);
    cudaGetSymbolAddress((void**)&y, g_y);
    cudaGetSymbolAddress((void**)&xt, g_xt);
    cudaGetSymbolAddress((void**)&wq, g_wq);
    cudaGetSymbolAddress((void**)&wo, g_wo);

    cudaFuncSetAttribute(mma_gemm_ca,
                         cudaFuncAttributeMaxDynamicSharedMemorySize, GEMM2_SMEM);
    cudaFuncSetAttribute(flash_attn_tc,
                         cudaFuncAttributeMaxDynamicSharedMemorySize, FA_SMEM);

    // 0) Pre-convert inputs to tf32 format
    {
        int n4x = (NROWS * Dn) / 4;
        conv_tf32_kernel<<<(n4x + 255) / 256, 256>>>(x, xt, n4x);
        int n4q = (TDn * Dn) / 4;
        conv_tf32_kernel<<<(n4q + 255) / 256, 256>>>(qkv_w, wq, n4q);
        int n4o = (Dn * Dn) / 4;
        conv_tf32_kernel<<<(n4o + 255) / 256, 256>>>(out_w, wo, n4o);
    }

    // 1) QKV projection (cp.async tf32 mma, 128x256 CTA tile)
    {
        dim3 grid(TDn / 256, NROWS / 128);
        mma_gemm_ca<<<grid, 256, GEMM2_SMEM>>>(xt, wq, qkv_b, qkv,
                                               NROWS, TDn, Dn);
    }

    // 2) RoPE on q,k
    {
        int total = Bn * Sn * Hn * (DHn / 2);
        rope_kernel<<<(total + 255) / 256, 256>>>(qkv);
    }

    // 3) Flash attention (tensor-core tf32), emits tf32-formatted y
    {
        dim3 grid(Sn / 128, Bn * Hn);
        flash_attn_tc<<<grid, 256, FA_SMEM>>>(qkv, y);
    }

    // 4) Output projection (cp.async tf32 mma, 128x256 CTA tile)
    {
        dim3 grid(Dn / 256, NROWS / 128);
        mma_gemm_ca<<<grid, 256, GEMM2_SMEM>>>(y, wo, out_b, out,
                                               NROWS, Dn, Dn);
    }
}

// round 7
// speedup vs baseline: 1.2132x; 1.2132x over previous
#include <cuda_runtime.h>
#include <cstdint>
#include <math.h>

// Problem constants
#define Bn 4
#define Sn 2048
#define Dn 2048
#define Hn 16
#define DHn 128
#define TDn 6144            // 3*D
#define NROWS (Bn*Sn)       // 8192

// Scratch (device globals; no cudaMalloc allowed)
__device__ float g_qkv[(size_t)NROWS * TDn];   // 201 MB
__device__ float g_y[(size_t)NROWS * Dn];      // 67 MB  (tf32-formatted)
__device__ float g_xt[(size_t)NROWS * Dn];     // 67 MB  x  pre-converted
__device__ float g_wq[(size_t)TDn * Dn];       // 50 MB  qkv_w pre-converted
__device__ float g_wo[(size_t)Dn * Dn];        // 17 MB  out_w pre-converted

__device__ __forceinline__ uint32_t f2tf32(float x) {
    uint32_t r;
    asm("cvt.rna.tf32.f32 %0, %1;" : "=r"(r) : "f"(x));
    return r;
}

__device__ __forceinline__ void mma_tf32(float* d,
                                         uint32_t a0, uint32_t a1,
                                         uint32_t a2, uint32_t a3,
                                         uint32_t b0, uint32_t b1) {
    asm volatile(
        "mma.sync.aligned.m16n8k8.row.col.f32.tf32.tf32.f32 "
        "{%0,%1,%2,%3}, {%4,%5,%6,%7}, {%8,%9}, {%0,%1,%2,%3};"
        : "+f"(d[0]), "+f"(d[1]), "+f"(d[2]), "+f"(d[3])
        : "r"(a0), "r"(a1), "r"(a2), "r"(a3), "r"(b0), "r"(b1));
}

__device__ __forceinline__ void cp16(void* smem_ptr, const void* gptr) {
    uint32_t sa = (uint32_t)__cvta_generic_to_shared(smem_ptr);
    asm volatile("cp.async.cg.shared.global [%0], [%1], 16;"
                 :: "r"(sa), "l"(gptr));
}
#define CP_COMMIT() asm volatile("cp.async.commit_group;" ::: "memory")
#define CP_WAIT(n)  asm volatile("cp.async.wait_group %0;" :: "n"(n) : "memory")

// ---------------------------------------------------------------------------
// Pre-convert fp32 -> tf32-formatted fp32 (vectorized)
// ---------------------------------------------------------------------------
__global__ __launch_bounds__(256) void conv_tf32_kernel(
    const float* __restrict__ in, float* __restrict__ out, int n4)
{
    int i = blockIdx.x * blockDim.x + threadIdx.x;
    if (i >= n4) return;
    float4 v = ((const float4*)in)[i];
    uint4 u = make_uint4(f2tf32(v.x), f2tf32(v.y), f2tf32(v.z), f2tf32(v.w));
    ((uint4*)out)[i] = u;
}

// ---------------------------------------------------------------------------
// cp.async tf32 GEMM: C[M,N] = A[M,K] @ W[N,K]^T + bias[N], optional fused RoPE
// CTA 128x128, 128 threads = 4 warps (2m x 2n), warp tile 64x64.
// KC=16, 4 stages, stride-20 smem (conflict-free). 2 CTAs/SM.
// ---------------------------------------------------------------------------
#define KC2 16
#define STG 4
#define STR2 20
#define ATILE (128 * STR2)                    // 2560 floats (10KB)
#define STAGE_F (2 * ATILE)
#define GEMM2_SMEM (STG * STAGE_F * 4)        // 81920 bytes

__global__ void __launch_bounds__(128, 2) mma_gemm_ca(
    const float* __restrict__ A, const float* __restrict__ W,
    const float* __restrict__ bias, float* __restrict__ C,
    int M, int N, int K, int rope_qk)
{
    extern __shared__ float sm[];
    const int tid = threadIdx.x;
    const int wid = tid >> 5;
    const int lid = tid & 31;
    const int g   = lid >> 2;
    const int tg  = lid & 3;
    const int wm  = wid >> 1;       // 0..1
    const int wn  = wid & 1;        // 0..1
    const int m0 = blockIdx.y << 7;
    const int n0 = blockIdx.x << 7;

    const float* Abase = A + (size_t)m0 * K;
    const float* Wbase = W + (size_t)n0 * K;

    // load mapping: 512 16B-slots per tile, 128 threads -> 4 iters each
    float acc[4][8][4];
#pragma unroll
    for (int mi = 0; mi < 4; mi++)
#pragma unroll
        for (int ni = 0; ni < 8; ni++)
#pragma unroll
            for (int r = 0; r < 4; r++) acc[mi][ni][r] = 0.f;

    const int nc = K / KC2;

    auto issue_load = [&](int stage, int chunk) {
        const int k0 = chunk * KC2;
        float* As = sm + stage * STAGE_F;
        float* Bs = As + ATILE;
#pragma unroll
        for (int i = 0; i < 4; i++) {
            const int idx = i * 128 + tid;
            const int row = idx >> 2;
            const int c4  = (idx & 3) << 2;
            cp16(&As[row * STR2 + c4], Abase + (size_t)row * K + k0 + c4);
            cp16(&Bs[row * STR2 + c4], Wbase + (size_t)row * K + k0 + c4);
        }
    };

    auto compute = [&](int stage) {
        const float* As = sm + stage * STAGE_F;
        const float* Bs = As + ATILE;
#pragma unroll
        for (int ks = 0; ks < 2; ks++) {
            const int kc = ks * 8;
            uint32_t bf[8][2];
#pragma unroll
            for (int ni = 0; ni < 8; ni++) {
                const float* bp = &Bs[(wn * 64 + ni * 8 + g) * STR2 + kc + tg];
                bf[ni][0] = __float_as_uint(bp[0]);
                bf[ni][1] = __float_as_uint(bp[4]);
            }
#pragma unroll
            for (int mi = 0; mi < 4; mi++) {
                const float* ap = &As[(wm * 64 + mi * 16 + g) * STR2 + kc + tg];
                uint32_t a0 = __float_as_uint(ap[0]);
                uint32_t a1 = __float_as_uint(ap[8 * STR2]);
                uint32_t a2 = __float_as_uint(ap[4]);
                uint32_t a3 = __float_as_uint(ap[8 * STR2 + 4]);
#pragma unroll
                for (int ni = 0; ni < 8; ni++)
                    mma_tf32(acc[mi][ni], a0, a1, a2, a3,
                             bf[ni][0], bf[ni][1]);
            }
        }
    };

    // prologue
#pragma unroll
    for (int s = 0; s < STG - 1; s++) {
        issue_load(s, s);
        CP_COMMIT();
    }

    for (int c = 0; c < nc; c++) {
        CP_WAIT(STG - 2);
        __syncthreads();
        const int nxt = c + STG - 1;
        if (nxt < nc) issue_load(nxt & (STG - 1), nxt);
        CP_COMMIT();
        compute(c & (STG - 1));
    }

    // epilogue: bias (+ optional RoPE on q,k columns), then store
    const bool do_rope = rope_qk && (n0 < 2 * Dn);   // CTA tile never straddles
#pragma unroll
    for (int ni = 0; ni < 8; ni++) {
        const int col = n0 + wn * 64 + ni * 8 + 2 * tg;
        const float2 bj = *(const float2*)&bias[col];
        float freq = 0.f, omega = 0.f;
        if (do_rope) {
            const int d2 = (col & 127) >> 1;
            freq = powf(10000.0f, -(float)d2 / 64.0f);
        }
#pragma unroll
        for (int mi = 0; mi < 4; mi++) {
            const int row = m0 + wm * 64 + mi * 16 + g;
            float2 o0, o1;
            o0.x = acc[mi][ni][0] + bj.x;
            o0.y = acc[mi][ni][1] + bj.y;
            o1.x = acc[mi][ni][2] + bj.x;
            o1.y = acc[mi][ni][3] + bj.y;
            if (do_rope) {
                float sn, cs;
                omega = (float)(row & (Sn - 1)) * freq;
                sincosf(omega, &sn, &cs);
                float r0x = o0.x * cs - o0.y * sn;
                float r0y = o0.x * sn + o0.y * cs;
                o0.x = r0x; o0.y = r0y;
                omega = (float)((row + 8) & (Sn - 1)) * freq;
                sincosf(omega, &sn, &cs);
                float r1x = o1.x * cs - o1.y * sn;
                float r1y = o1.x * sn + o1.y * cs;
                o1.x = r1x; o1.y = r1y;
            }
            *(float2*)&C[(size_t)row * N + col] = o0;
            *(float2*)&C[(size_t)(row + 8) * N + col] = o1;
        }
    }
}

// ---------------------------------------------------------------------------
// Tensor-core flash attention (causal), tf32 mma. (unchanged R5)
// ---------------------------------------------------------------------------
#define KSTR 132
#define VSTR 136
#define PSTRW 132
#define FA_SMEM ((64 * KSTR + 64 * VSTR + 128 * PSTRW) * 4)

__global__ __launch_bounds__(256) void flash_attn_tc(
    const float* __restrict__ qkv, float* __restrict__ Y)
{
    extern __shared__ float sm[];
    float* Ks = sm;
    float* Vs = Ks + 64 * KSTR;
    float* Pw = Vs + 64 * VSTR;

    const int tid = threadIdx.x;
    const int wid = tid >> 5;
    const int lid = tid & 31;
    const int g   = lid >> 2;
    const int tg  = lid & 3;
    const int qb  = blockIdx.x;
    const int q0  = qb * 128;
    const int bh  = blockIdx.y;
    const int b   = bh >> 4;
    const int h   = bh & 15;

    const int row0 = q0 + wid * 16 + g;
    const float scale = 0.08838834764831845f;

    const float* qptr = qkv + ((size_t)(b * Sn + row0)) * TDn + h * DHn;
    uint32_t qf[16][4];
#pragma unroll
    for (int kt = 0; kt < 16; kt++) {
        qf[kt][0] = f2tf32(qptr[kt * 8 + tg] * scale);
        qf[kt][1] = f2tf32(qptr[(size_t)8 * TDn + kt * 8 + tg] * scale);
        qf[kt][2] = f2tf32(qptr[kt * 8 + tg + 4] * scale);
        qf[kt][3] = f2tf32(qptr[(size_t)8 * TDn + kt * 8 + tg + 4] * scale);
    }

    float ofr[16][4];
#pragma unroll
    for (int nt = 0; nt < 16; nt++)
#pragma unroll
        for (int r = 0; r < 4; r++) ofr[nt][r] = 0.f;

    float m0 = -1e30f, m1 = -1e30f, l0 = 0.f, l1 = 0.f;

    const float* kbase = qkv + ((size_t)(b * Sn)) * TDn + Dn + h * DHn;
    const float* vbase = kbase + Dn;
    float* prow = Pw + (wid * 16) * PSTRW;

    const int nkb = 2 * qb + 2;
    for (int kb = 0; kb < nkb; kb++) {
        __syncthreads();
        const int k0 = kb * 64;

#pragma unroll
        for (int i = 0; i < 8; i++) {
            int idx = tid + i * 256;
            int r  = idx >> 5;
            int c4 = (idx & 31) << 2;
            const size_t go = (size_t)(k0 + r) * TDn + c4;
            float4 kv = *(const float4*)(kbase + go);
            uint4 ku = make_uint4(f2tf32(kv.x), f2tf32(kv.y),
                                  f2tf32(kv.z), f2tf32(kv.w));
            *(uint4*)&Ks[r * KSTR + c4] = ku;
            float4 vv = *(const float4*)(vbase + go);
            uint4 vu = make_uint4(f2tf32(vv.x), f2tf32(vv.y),
                                  f2tf32(vv.z), f2tf32(vv.w));
            *(uint4*)&Vs[r * VSTR + c4] = vu;
        }
        __syncthreads();

        float sc[8][4];
#pragma unroll
        for (int nt = 0; nt < 8; nt++)
#pragma unroll
            for (int r = 0; r < 4; r++) sc[nt][r] = 0.f;

#pragma unroll
        for (int kt = 0; kt < 16; kt++) {
#pragma unroll
            for (int nt = 0; nt < 8; nt++) {
                const float* bp = &Ks[(nt * 8 + g) * KSTR + kt * 8 + tg];
                uint32_t b0 = __float_as_uint(bp[0]);
                uint32_t b1 = __float_as_uint(bp[4]);
                mma_tf32(sc[nt], qf[kt][0], qf[kt][1], qf[kt][2], qf[kt][3],
                         b0, b1);
            }
        }

        if (kb >= 2 * qb) {
#pragma unroll
            for (int nt = 0; nt < 8; nt++) {
                int col = k0 + nt * 8 + 2 * tg;
                if (col > row0)     sc[nt][0] = -1e30f;
                if (col + 1 > row0) sc[nt][1] = -1e30f;
                if (col > row0 + 8)     sc[nt][2] = -1e30f;
                if (col + 1 > row0 + 8) sc[nt][3] = -1e30f;
            }
        }

        float mx0 = -1e30f, mx1 = -1e30f;
#pragma unroll
        for (int nt = 0; nt < 8; nt++) {
            mx0 = fmaxf(mx0, fmaxf(sc[nt][0], sc[nt][1]));
            mx1 = fmaxf(mx1, fmaxf(sc[nt][2], sc[nt][3]));
        }
        mx0 = fmaxf(mx0, __shfl_xor_sync(0xffffffffu, mx0, 1));
        mx0 = fmaxf(mx0, __shfl_xor_sync(0xffffffffu, mx0, 2));
        mx1 = fmaxf(mx1, __shfl_xor_sync(0xffffffffu, mx1, 1));
        mx1 = fmaxf(mx1, __shfl_xor_sync(0xffffffffu, mx1, 2));

        const float mn0 = fmaxf(m0, mx0);
        const float mn1 = fmaxf(m1, mx1);
        const float a0 = __expf(m0 - mn0);
        const float a1 = __expf(m1 - mn1);
        m0 = mn0; m1 = mn1;

        float s0 = 0.f, s1 = 0.f;
#pragma unroll
        for (int nt = 0; nt < 8; nt++) {
            sc[nt][0] = __expf(sc[nt][0] - mn0);
            sc[nt][1] = __expf(sc[nt][1] - mn0);
            sc[nt][2] = __expf(sc[nt][2] - mn1);
            sc[nt][3] = __expf(sc[nt][3] - mn1);
            s0 += sc[nt][0] + sc[nt][1];
            s1 += sc[nt][2] + sc[nt][3];
        }
        s0 += __shfl_xor_sync(0xffffffffu, s0, 1);
        s0 += __shfl_xor_sync(0xffffffffu, s0, 2);
        s1 += __shfl_xor_sync(0xffffffffu, s1, 1);
        s1 += __shfl_xor_sync(0xffffffffu, s1, 2);
        l0 = l0 * a0 + s0;
        l1 = l1 * a1 + s1;

#pragma unroll
        for (int nt = 0; nt < 16; nt++) {
            ofr[nt][0] *= a0; ofr[nt][1] *= a0;
            ofr[nt][2] *= a1; ofr[nt][3] *= a1;
        }

        __syncwarp();
#pragma unroll
        for (int nt = 0; nt < 8; nt++) {
            const int col = nt * 8 + 2 * tg;
            prow[g * PSTRW + col]           = __uint_as_float(f2tf32(sc[nt][0]));
            prow[g * PSTRW + col + 1]       = __uint_as_float(f2tf32(sc[nt][1]));
            prow[(g + 8) * PSTRW + col]     = __uint_as_float(f2tf32(sc[nt][2]));
            prow[(g + 8) * PSTRW + col + 1] = __uint_as_float(f2tf32(sc[nt][3]));
        }
        __syncwarp();

#pragma unroll
        for (int kt = 0; kt < 8; kt++) {
            uint32_t pa0 = __float_as_uint(prow[g * PSTRW + kt * 8 + tg]);
            uint32_t pa1 = __float_as_uint(prow[(g + 8) * PSTRW + kt * 8 + tg]);
            uint32_t pa2 = __float_as_uint(prow[g * PSTRW + kt * 8 + tg + 4]);
            uint32_t pa3 = __float_as_uint(prow[(g + 8) * PSTRW + kt * 8 + tg + 4]);
#pragma unroll
            for (int nt = 0; nt < 16; nt++) {
                uint32_t b0 = __float_as_uint(Vs[(kt * 8 + tg) * VSTR + nt * 8 + g]);
                uint32_t b1 = __float_as_uint(Vs[(kt * 8 + tg + 4) * VSTR + nt * 8 + g]);
                mma_tf32(ofr[nt], pa0, pa1, pa2, pa3, b0, b1);
            }
        }
    }

    const float inv0 = 1.0f / l0;
    const float inv1 = 1.0f / l1;
    float* yrow = Y + ((size_t)(b * Sn + row0)) * Dn + h * DHn;
#pragma unroll
    for (int nt = 0; nt < 16; nt++) {
        const int col = nt * 8 + 2 * tg;
        float2 o0, o1;
        o0.x = __uint_as_float(f2tf32(ofr[nt][0] * inv0));
        o0.y = __uint_as_float(f2tf32(ofr[nt][1] * inv0));
        o1.x = __uint_as_float(f2tf32(ofr[nt][2] * inv1));
        o1.y = __uint_as_float(f2tf32(ofr[nt][3] * inv1));
        *(float2*)&yrow[col] = o0;
        *(float2*)&yrow[(size_t)8 * Dn + col] = o1;
    }
}

// ---------------------------------------------------------------------------
extern "C" void kernel_launch(void* const* d_in, const int* in_sizes, int n_in,
                              void* d_out, int out_size)
{
    (void)in_sizes; (void)n_in; (void)out_size;
    const float* x      = (const float*)d_in[0];
    const float* qkv_w  = (const float*)d_in[1];
    const float* qkv_b  = (const float*)d_in[2];
    const float* out_w  = (const float*)d_in[3];
    const float* out_b  = (const float*)d_in[4];
    float* out = (float*)d_out;

    float *qkv, *y, *xt, *wq, *wo;
    cudaGetSymbolAddress((void**)&qkv, g_qkv);
    cudaGetSymbolAddress((void**)&y, g_y);
    cudaGetSymbolAddress((void**)&xt, g_xt);
    cudaGetSymbolAddress((void**)&wq, g_wq);
    cudaGetSymbolAddress((void**)&wo, g_wo);

    cudaFuncSetAttribute(mma_gemm_ca,
                         cudaFuncAttributeMaxDynamicSharedMemorySize, GEMM2_SMEM);
    cudaFuncSetAttribute(flash_attn_tc,
                         cudaFuncAttributeMaxDynamicSharedMemorySize, FA_SMEM);

    // 0) Pre-convert inputs to tf32 format
    {
        int n4x = (NROWS * Dn) / 4;
        conv_tf32_kernel<<<(n4x + 255) / 256, 256>>>(x, xt, n4x);
        int n4q = (TDn * Dn) / 4;
        conv_tf32_kernel<<<(n4q + 255) / 256, 256>>>(qkv_w, wq, n4q);
        int n4o = (Dn * Dn) / 4;
        conv_tf32_kernel<<<(n4o + 255) / 256, 256>>>(out_w, wo, n4o);
    }

    // 1) QKV projection + fused RoPE (cp.async tf32 mma, 128-thread CTA)
    {
        dim3 grid(TDn / 128, NROWS / 128);
        mma_gemm_ca<<<grid, 128, GEMM2_SMEM>>>(xt, wq, qkv_b, qkv,
                                               NROWS, TDn, Dn, 1);
    }

    // 2) Flash attention (tensor-core tf32), emits tf32-formatted y
    {
        dim3 grid(Sn / 128, Bn * Hn);
        flash_attn_tc<<<grid, 256, FA_SMEM>>>(qkv, y);
    }

    // 3) Output projection (cp.async tf32 mma)
    {
        dim3 grid(Dn / 128, NROWS / 128);
        mma_gemm_ca<<<grid, 128, GEMM2_SMEM>>>(y, wo, out_b, out,
                                               NROWS, Dn, Dn, 0);
    }
}